// round 15
// baseline (speedup 1.0000x reference)
#include <cuda_runtime.h>
#include <cuda_bf16.h>
#include <cstdint>

#define N_RAYS 131072
#define IN_DIM 1024

// ---- global scratch (static: no runtime allocation) ----
__device__ __nv_bfloat16 g_w1t_hi[64 * IN_DIM];   // [n][k]
__device__ __nv_bfloat16 g_w1t_lo[64 * IN_DIM];

// ---- packed f32x2 helpers ----
#define FMA2(d, a, b) asm("fma.rn.f32x2 %0, %1, %2, %0;" : "+l"(d) : "l"(a), "l"(b))
#define MUL2(d, a, b) asm("mul.rn.f32x2 %0, %1, %2;"     : "=l"(d) : "l"(a), "l"(b))
#define PACK2(d, s)   asm("mov.b64 %0, {%1, %1};"        : "=l"(d) : "r"(s))
#define UNPK2(lo, hi, d) asm("mov.b64 {%0, %1}, %2;" : "=f"(lo), "=f"(hi) : "l"(d))

__device__ __forceinline__ void cp_async16(uint32_t dst, const void* src) {
    asm volatile("cp.async.cg.shared.global [%0], [%1], 16;\n" :: "r"(dst), "l"(src));
}
__device__ __forceinline__ void cp_commit() { asm volatile("cp.async.commit_group;\n"); }
__device__ __forceinline__ void cp_wait0()  { asm volatile("cp.async.wait_group 0;\n"); }
__device__ __forceinline__ void cp_wait1()  { asm volatile("cp.async.wait_group 1;\n"); }
__device__ __forceinline__ uint32_t smem_u32(const void* p) {
    uint32_t a;
    asm("{ .reg .u64 t; cvta.to.shared.u64 t, %1; cvt.u32.u64 %0, t; }" : "=r"(a) : "l"(p));
    return a;
}

#define MMA_BF16(d, a, b) \
    asm volatile("mma.sync.aligned.m16n8k16.row.col.f32.bf16.bf16.f32 " \
        "{%0,%1,%2,%3}, {%4,%5,%6,%7}, {%8,%9}, {%0,%1,%2,%3};" \
        : "+f"((d)[0]), "+f"((d)[1]), "+f"((d)[2]), "+f"((d)[3]) \
        : "r"((a)[0]), "r"((a)[1]), "r"((a)[2]), "r"((a)[3]), \
          "r"((b)[0]), "r"((b)[1]))

__device__ __forceinline__ void ldsm4(uint32_t* r, uint32_t addr) {
    asm volatile("ldmatrix.sync.aligned.m8n8.x4.shared.b16 {%0,%1,%2,%3}, [%4];"
        : "=r"(r[0]), "=r"(r[1]), "=r"(r[2]), "=r"(r[3]) : "r"(addr));
}

// ===================================================================
// Kernel 0: transpose W1 -> bf16 hi/lo planes [n][k]
// ===================================================================
__global__ void prep_w(const float* __restrict__ W1) {
    int idx = blockIdx.x * 1024 + threadIdx.x;
    int n = idx >> 10, k = idx & 1023;
    float v = W1[k * 64 + n];
    __nv_bfloat16 hi = __float2bfloat16(v);
    __nv_bfloat16 lo = __float2bfloat16(v - __bfloat162float(hi));
    g_w1t_hi[idx] = hi;
    g_w1t_lo[idx] = lo;
}

// ===================================================================
// Fused kernel: gather + interp -> smem bf16 planes -> mma -> MLP
// ===================================================================
#define THREADS 512
#define RAYS_CTA 128
#define RS 272                  // A/B row stride (bytes), 17*16 -> ldmatrix conflict-free
#define ESTRIDE 132             // emb row stride (floats), 528 B = 33*16

// smem layout (bytes)
#define S_NODES 0                         // 1024 ints        (4096)
#define S_PP    4096                      // 1024 * 6 floats  (24576)
#define S_EBUF  28672                     // 128 * 528        (67584)
#define S_A     96256                     // 2 * 128 * 272    (69632)
#define S_B     165888                    // 2 * 64 * 272     (34816)
#define SMEM_BYTES 200704
#define APLANE  (128 * RS)                // 34816
#define BPLANE  (64 * RS)                 // 17408
#define H1S 68                            // h1 stride (floats)

__global__ void __launch_bounds__(THREADS) fused_kernel(
    const float* __restrict__ orig, const float* __restrict__ endp,
    const int* __restrict__ history32,
    const float* __restrict__ nodes_min, const float* __restrict__ nodes_extent,
    const float* __restrict__ emb,
    const float* __restrict__ W2, const float* __restrict__ W3,
    float* __restrict__ out)
{
    extern __shared__ char smc[];
    const uint32_t smem_base = smem_u32(smc);
    int*   nodes = (int*)(smc + S_NODES);
    float* pp    = (float*)(smc + S_PP);
    float* ebuf  = (float*)(smc + S_EBUF);

    const int tid  = threadIdx.x;
    const int ray0 = blockIdx.x * RAYS_CTA;

    const int hstride =
        (history32[1] == 0 && history32[3] == 0 &&
         history32[5] == 0 && history32[7] == 0) ? 2 : 1;

    // ---- prologue: node ids + clipped entry/exit for all (ray, depth) ----
    #pragma unroll
    for (int it = 0; it < 2; ++it) {
        int item = tid + it * THREADS;          // (ray, d)
        int lr = item >> 3, d = item & 7;
        int ray = ray0 + lr;
        int node = history32[(size_t)(ray * 8 + d) * hstride];
        nodes[item] = node;

        float nx = nodes_min[node * 3 + 0], ny = nodes_min[node * 3 + 1], nz = nodes_min[node * 3 + 2];
        float sx = nodes_extent[node * 3 + 0], sy = nodes_extent[node * 3 + 1], sz = nodes_extent[node * 3 + 2];
        float ox = orig[ray * 3 + 0], oy = orig[ray * 3 + 1], oz = orig[ray * 3 + 2];
        float ex = endp[ray * 3 + 0], ey = endp[ray * 3 + 1], ez = endp[ray * 3 + 2];

        float* q = pp + item * 6;
        q[0] = fminf(fmaxf((ox - nx) / sx, 0.f), 1.f);
        q[1] = fminf(fmaxf((oy - ny) / sy, 0.f), 1.f);
        q[2] = fminf(fmaxf((oz - nz) / sz, 0.f), 1.f);
        q[3] = fminf(fmaxf((ex - nx) / sx, 0.f), 1.f);
        q[4] = fminf(fmaxf((ey - ny) / sy, 0.f), 1.f);
        q[5] = fminf(fmaxf((ez - nz) / sz, 0.f), 1.f);
    }
    __syncthreads();

    // ---- loaders ----
    auto load_emb = [&](int d) {   // 128 rays x 512 B
        #pragma unroll
        for (int it = 0; it < 8; ++it) {
            int i = tid + it * THREADS;
            int row = i >> 5, l = i & 31;
            const float* src = emb + (size_t)nodes[row * 8 + d] * 128 + l * 4;
            cp_async16(smem_base + S_EBUF + row * (ESTRIDE * 4) + l * 16, src);
        }
        cp_commit();
    };
    auto load_B = [&](int d) {     // 2 planes x 64 rows x 256 B
        #pragma unroll
        for (int it = 0; it < 4; ++it) {
            int i = tid + it * THREADS;
            int plane = i >> 10, rem = i & 1023;
            int row = rem >> 4, j = rem & 15;
            const __nv_bfloat16* base = plane ? g_w1t_lo : g_w1t_hi;
            cp_async16(smem_base + S_B + plane * BPLANE + row * RS + j * 16,
                       base + (size_t)row * 1024 + d * 128 + j * 8);
        }
        cp_commit();
    };

    load_emb(0);   // group E0
    load_B(0);     // group B0

    // MMA mapping: 16 warps, warp tile 16 rows x 32 cols
    const int warp = tid >> 5, lane = tid & 31;
    const int wm = warp & 7, wn = warp >> 3;
    const int gid = lane >> 2, qp = lane & 3;
    const uint32_t aoff = (uint32_t)((wm * 16 + (lane & 15)) * RS + (lane >> 4) * 16);
    const uint32_t boff = (uint32_t)((wn * 32 + (lane >> 4) * 8 + (lane & 7)) * RS
                                     + ((lane >> 3) & 1) * 16);

    float acc[4][4];
    #pragma unroll
    for (int nt = 0; nt < 4; ++nt)
        #pragma unroll
        for (int v = 0; v < 4; ++v) acc[nt][v] = 0.f;

    for (int d = 0; d < 8; ++d) {
        // emb(d) ready (older of the <=2 outstanding groups)
        cp_wait1();
        __syncthreads();

        // ---- interp: item = (ray, p), 16 feats each -> A planes (bf16 hi/lo) ----
        #pragma unroll
        for (int it = 0; it < 2; ++it) {
            int item = tid + it * THREADS;
            int ray = item >> 3, p = item & 7;
            const float* q = pp + (ray * 8 + d) * 6;
            float pox = q[0], poy = q[1], poz = q[2];
            float t = (float)p * (1.0f / 7.0f);
            float x = pox + (q[3] - pox) * t;
            float y = poy + (q[4] - poy) * t;
            float z = poz + (q[5] - poz) * t;
            float mx = 1.f - x, my = 1.f - y, mz = 1.f - z;
            float wsc[8];
            wsc[0] = mx * my * mz; wsc[1] = x * my * mz;
            wsc[2] = mx * y * mz;  wsc[3] = mx * my * z;
            wsc[4] = x * my * z;   wsc[5] = mx * y * z;
            wsc[6] = x * y * mz;   wsc[7] = x * y * z;
            unsigned long long pw[8];
            #pragma unroll
            for (int c = 0; c < 8; ++c) PACK2(pw[c], __float_as_uint(wsc[c]));

            const float* er = ebuf + ray * ESTRIDE;
            float f[16];
            #pragma unroll
            for (int g = 0; g < 2; ++g) {   // halves of 8 feats
                ulonglong2 e[8];
                #pragma unroll
                for (int c = 0; c < 8; ++c)
                    e[c] = *(const ulonglong2*)(er + c * 16 + g * 8);
                unsigned long long a0, a1;
                MUL2(a0, pw[0], e[0].x);
                MUL2(a1, pw[0], e[0].y);
                #pragma unroll
                for (int c = 1; c < 8; ++c) {
                    FMA2(a0, pw[c], e[c].x);
                    FMA2(a1, pw[c], e[c].y);
                }
                UNPK2(f[g * 8 + 0], f[g * 8 + 1], a0);
                UNPK2(f[g * 8 + 2], f[g * 8 + 3], a1);
                ulonglong2 e2[8];
                #pragma unroll
                for (int c = 0; c < 8; ++c)
                    e2[c] = *(const ulonglong2*)(er + c * 16 + g * 8 + 4);
                MUL2(a0, pw[0], e2[0].x);
                MUL2(a1, pw[0], e2[0].y);
                #pragma unroll
                for (int c = 1; c < 8; ++c) {
                    FMA2(a0, pw[c], e2[c].x);
                    FMA2(a1, pw[c], e2[c].y);
                }
                UNPK2(f[g * 8 + 4], f[g * 8 + 5], a0);
                UNPK2(f[g * 8 + 6], f[g * 8 + 7], a1);
            }
            union { __nv_bfloat16 h[16]; uint4 q4[2]; } H, L;
            #pragma unroll
            for (int i = 0; i < 16; ++i) {
                H.h[i] = __float2bfloat16(f[i]);
                L.h[i] = __float2bfloat16(f[i] - __bfloat162float(H.h[i]));
            }
            uint32_t dst = smem_base + S_A + ray * RS + p * 32;
            *(uint4*)(smc + (dst - smem_base))          = H.q4[0];
            *(uint4*)(smc + (dst - smem_base) + 16)     = H.q4[1];
            *(uint4*)(smc + (dst - smem_base) + APLANE)      = L.q4[0];
            *(uint4*)(smc + (dst - smem_base) + APLANE + 16) = L.q4[1];
        }
        __syncthreads();

        if (d < 7) load_emb(d + 1);   // ebuf free; overlap with MMA

        // B(d) ready (older group); keep emb(d+1) in flight
        if (d < 7) cp_wait1(); else cp_wait0();
        __syncthreads();

        // ---- MMA: A(128x128) x B(64x128), 3 bf16 terms ----
        {
            uint32_t ahi = smem_base + S_A, alo = ahi + APLANE;
            uint32_t bhi = smem_base + S_B, blo = bhi + BPLANE;
            #pragma unroll
            for (int ks = 0; ks < 8; ++ks) {
                uint32_t kb = ks * 32;
                uint32_t aH[4], aL[4], bH[8], bL[8];
                ldsm4(aH, ahi + aoff + kb);
                ldsm4(aL, alo + aoff + kb);
                #pragma unroll
                for (int np = 0; np < 2; ++np) {
                    ldsm4(bH + np * 4, bhi + boff + np * 16 * RS + kb);
                    ldsm4(bL + np * 4, blo + boff + np * 16 * RS + kb);
                }
                #pragma unroll
                for (int nt = 0; nt < 4; ++nt) {
                    MMA_BF16(acc[nt], aH, bH + nt * 2);
                    MMA_BF16(acc[nt], aL, bH + nt * 2);
                    MMA_BF16(acc[nt], aH, bL + nt * 2);
                }
            }
        }
        __syncthreads();

        if (d < 7) load_B(d + 1);     // B buffer free; overlap with next interp
    }

    // ---- epilogue: h1 relu -> smem; SIMT fp32 W2/W3 ----
    float* h1buf = (float*)(smc + S_EBUF);
    float* wbuf  = (float*)(smc + S_A);
    float* sw3   = (float*)(smc + S_PP);
    #pragma unroll
    for (int nt = 0; nt < 4; ++nt) {
        int col = wn * 32 + nt * 8 + qp * 2;
        #pragma unroll
        for (int half = 0; half < 2; ++half) {
            int row = wm * 16 + half * 8 + gid;
            float2 v;
            v.x = fmaxf(acc[nt][half * 2 + 0], 0.f);
            v.y = fmaxf(acc[nt][half * 2 + 1], 0.f);
            *(float2*)(h1buf + row * H1S + col) = v;
        }
    }
    {
        const float4* w4 = (const float4*)W2;
        float4* wd = (float4*)wbuf;
        #pragma unroll
        for (int it = 0; it < 2; ++it)
            wd[tid + it * THREADS] = w4[tid + it * THREADS];
        if (tid < 128) sw3[tid] = W3[tid];
    }
    __syncthreads();

    if (tid < 256) {
        int lray = tid >> 1, half = tid & 1, c0 = half * 32;
        float a32[32];
        #pragma unroll
        for (int j = 0; j < 32; ++j) a32[j] = 0.f;
        #pragma unroll 4
        for (int k = 0; k < 64; ++k) {
            float hv = h1buf[lray * H1S + k];
            const float* wr = wbuf + k * 64 + c0;
            #pragma unroll
            for (int j = 0; j < 32; ++j)
                a32[j] = fmaf(hv, wr[j], a32[j]);
        }
        float o0 = 0.f, o1 = 0.f;
        #pragma unroll
        for (int j = 0; j < 32; ++j) {
            float v = fmaxf(a32[j], 0.f);
            int col = c0 + j;
            o0 = fmaf(v, sw3[col * 2 + 0], o0);
            o1 = fmaf(v, sw3[col * 2 + 1], o1);
        }
        o0 += __shfl_xor_sync(0xFFFFFFFFu, o0, 1);
        o1 += __shfl_xor_sync(0xFFFFFFFFu, o1, 1);
        if (half == 0) {
            int ray = ray0 + lray;
            float dx = endp[ray * 3 + 0] - orig[ray * 3 + 0];
            float dy = endp[ray * 3 + 1] - orig[ray * 3 + 1];
            float dz = endp[ray * 3 + 2] - orig[ray * 3 + 2];
            float len = sqrtf(dx * dx + dy * dy + dz * dz);
            out[ray * 2 + 0] = o0;
            out[ray * 2 + 1] = o1 * len;
        }
    }
}

// ===================================================================
extern "C" void kernel_launch(void* const* d_in, const int* in_sizes, int n_in,
                              void* d_out, int out_size) {
    (void)in_sizes; (void)n_in; (void)out_size;
    const float* orig         = (const float*)d_in[0];
    const float* endp         = (const float*)d_in[1];
    const int*   history      = (const int*)d_in[2];
    const float* nodes_min    = (const float*)d_in[3];
    const float* nodes_extent = (const float*)d_in[4];
    const float* emb          = (const float*)d_in[5];
    const float* W1           = (const float*)d_in[6];
    const float* W2           = (const float*)d_in[7];
    const float* W3           = (const float*)d_in[8];
    float*       out          = (float*)d_out;

    static int inited = 0;
    if (!inited) {
        cudaFuncSetAttribute(fused_kernel, cudaFuncAttributeMaxDynamicSharedMemorySize, SMEM_BYTES);
        inited = 1;
    }

    prep_w<<<64, 1024>>>(W1);
    fused_kernel<<<N_RAYS / RAYS_CTA, THREADS, SMEM_BYTES>>>(
        orig, endp, history, nodes_min, nodes_extent, emb, W2, W3, out);
}